// round 1
// baseline (speedup 1.0000x reference)
#include <cuda_runtime.h>

#define N_NODES 50000
#define N_EDGES 600000
#define IN_F    256
#define OUT_F   128

// Scratch for support = x @ W  (25.6 MB)
__device__ float g_support[(size_t)N_NODES * OUT_F];

// ---------------------------------------------------------------------------
// SGEMM: support[M=50000, N=128] = x[M, K=256] @ W[K=256, N=128]
// 128x128 block tile, BK=16, 256 threads, 8x8 per-thread register tile.
// ---------------------------------------------------------------------------
__global__ __launch_bounds__(256) void gcn_sgemm_kernel(
    const float* __restrict__ x,
    const float* __restrict__ w)
{
    const int BM = 128;
    const int BK = 16;

    __shared__ float As[BK][BM];     // x tile, transposed: As[k][m]
    __shared__ float Bs[BK][OUT_F];  // W tile: Bs[k][n]

    const int tid = threadIdx.x;
    const int block_row = blockIdx.x * BM;

    const int tx = tid & 15;   // 0..15 -> col group (8 cols each)
    const int ty = tid >> 4;   // 0..15 -> row group (8 rows each)

    // A-tile load mapping: thread loads 8 floats of a 128x16 tile
    const int a_row = tid >> 1;          // 0..127
    const int a_col = (tid & 1) * 8;     // 0 or 8

    // B-tile load mapping: thread loads 8 floats of a 16x128 tile
    const int b_row = tid >> 4;          // 0..15
    const int b_col = (tid & 15) * 8;    // 0..120

    float acc[8][8];
    #pragma unroll
    for (int i = 0; i < 8; i++)
        #pragma unroll
        for (int j = 0; j < 8; j++)
            acc[i][j] = 0.0f;

    const int g_arow = block_row + a_row;
    const bool a_valid = (g_arow < N_NODES);

    for (int kt = 0; kt < IN_F; kt += BK) {
        // Load A tile (x): rows [block_row, block_row+128), cols [kt, kt+16)
        {
            float4 v0, v1;
            if (a_valid) {
                const float* xp = x + (size_t)g_arow * IN_F + kt + a_col;
                v0 = *(const float4*)(xp);
                v1 = *(const float4*)(xp + 4);
            } else {
                v0 = make_float4(0.f, 0.f, 0.f, 0.f);
                v1 = v0;
            }
            As[a_col + 0][a_row] = v0.x;
            As[a_col + 1][a_row] = v0.y;
            As[a_col + 2][a_row] = v0.z;
            As[a_col + 3][a_row] = v0.w;
            As[a_col + 4][a_row] = v1.x;
            As[a_col + 5][a_row] = v1.y;
            As[a_col + 6][a_row] = v1.z;
            As[a_col + 7][a_row] = v1.w;
        }
        // Load B tile (W): rows [kt, kt+16), cols [0, 128)
        {
            const float* wp = w + (size_t)(kt + b_row) * OUT_F + b_col;
            float4 v0 = *(const float4*)(wp);
            float4 v1 = *(const float4*)(wp + 4);
            *(float4*)(&Bs[b_row][b_col])     = v0;
            *(float4*)(&Bs[b_row][b_col + 4]) = v1;
        }
        __syncthreads();

        #pragma unroll
        for (int k = 0; k < BK; k++) {
            float a[8], b[8];
            float4 av0 = *(const float4*)(&As[k][ty * 8]);
            float4 av1 = *(const float4*)(&As[k][ty * 8 + 4]);
            float4 bv0 = *(const float4*)(&Bs[k][tx * 8]);
            float4 bv1 = *(const float4*)(&Bs[k][tx * 8 + 4]);
            a[0]=av0.x; a[1]=av0.y; a[2]=av0.z; a[3]=av0.w;
            a[4]=av1.x; a[5]=av1.y; a[6]=av1.z; a[7]=av1.w;
            b[0]=bv0.x; b[1]=bv0.y; b[2]=bv0.z; b[3]=bv0.w;
            b[4]=bv1.x; b[5]=bv1.y; b[6]=bv1.z; b[7]=bv1.w;
            #pragma unroll
            for (int i = 0; i < 8; i++)
                #pragma unroll
                for (int j = 0; j < 8; j++)
                    acc[i][j] = fmaf(a[i], b[j], acc[i][j]);
        }
        __syncthreads();
    }

    // Store to g_support
    #pragma unroll
    for (int i = 0; i < 8; i++) {
        const int gr = block_row + ty * 8 + i;
        if (gr < N_NODES) {
            float* sp = g_support + (size_t)gr * OUT_F + tx * 8;
            float4 v0 = make_float4(acc[i][0], acc[i][1], acc[i][2], acc[i][3]);
            float4 v1 = make_float4(acc[i][4], acc[i][5], acc[i][6], acc[i][7]);
            *(float4*)(sp)     = v0;
            *(float4*)(sp + 4) = v1;
        }
    }
}

// ---------------------------------------------------------------------------
// Init out with broadcast bias: out[n, f] = bias[f]
// ---------------------------------------------------------------------------
__global__ void gcn_init_out_kernel(float* __restrict__ out,
                                    const float* __restrict__ bias)
{
    int i = blockIdx.x * blockDim.x + threadIdx.x;   // float4 index
    const int total4 = N_NODES * OUT_F / 4;
    if (i < total4) {
        const float4* b4 = (const float4*)bias;
        ((float4*)out)[i] = b4[i & (OUT_F / 4 - 1)];
    }
}

// ---------------------------------------------------------------------------
// Edge scatter: out[r] += val * support[c], one warp per edge.
// Lane l handles output features [4l, 4l+4).
// ---------------------------------------------------------------------------
__global__ __launch_bounds__(256) void gcn_scatter_kernel(
    const int*   __restrict__ edge_rows,
    const int*   __restrict__ edge_cols,
    const float* __restrict__ edge_vals,
    float*       __restrict__ out)
{
    const int warp_id = (blockIdx.x * blockDim.x + threadIdx.x) >> 5;
    const int lane    = threadIdx.x & 31;
    if (warp_id >= N_EDGES) return;

    const int   r = edge_rows[warp_id];
    const int   c = edge_cols[warp_id];
    const float v = edge_vals[warp_id];

    const float4 m = ((const float4*)(g_support + (size_t)c * OUT_F))[lane];
    float* o = out + (size_t)r * OUT_F + lane * 4;
    atomicAdd(o + 0, v * m.x);
    atomicAdd(o + 1, v * m.y);
    atomicAdd(o + 2, v * m.z);
    atomicAdd(o + 3, v * m.w);
}

// ---------------------------------------------------------------------------
// kernel_launch
// Inputs (metadata order): x, edge_rows, edge_cols, edge_vals, weight, bias
// ---------------------------------------------------------------------------
extern "C" void kernel_launch(void* const* d_in, const int* in_sizes, int n_in,
                              void* d_out, int out_size)
{
    const float* x         = (const float*)d_in[0];
    const int*   edge_rows = (const int*)  d_in[1];
    const int*   edge_cols = (const int*)  d_in[2];
    const float* edge_vals = (const float*)d_in[3];
    const float* weight    = (const float*)d_in[4];
    const float* bias      = (const float*)d_in[5];
    float*       out       = (float*)d_out;

    // 1) support = x @ W
    {
        dim3 grid((N_NODES + 127) / 128);
        gcn_sgemm_kernel<<<grid, 256>>>(x, weight);
    }
    // 2) out = bias (broadcast)
    {
        const int total4 = N_NODES * OUT_F / 4;
        gcn_init_out_kernel<<<(total4 + 255) / 256, 256>>>(out, bias);
    }
    // 3) out[r] += val * support[c] per edge
    {
        const int warps_per_block = 256 / 32;
        const int blocks = (N_EDGES + warps_per_block - 1) / warps_per_block;
        gcn_scatter_kernel<<<blocks, 256>>>(edge_rows, edge_cols, edge_vals, out);
    }
}

// round 2
// speedup vs baseline: 1.0070x; 1.0070x over previous
#include <cuda_runtime.h>

#define N_NODES 50000
#define N_EDGES 600000
#define IN_F    256
#define OUT_F   128

// Scratch for support = x @ W  (25.6 MB)
__device__ float g_support[(size_t)N_NODES * OUT_F];

// ---------------------------------------------------------------------------
// SGEMM: support[M=50000, N=128] = x[M, K=256] @ W[K=256, N=128]
// 128x128 block tile, BK=16, 256 threads, 8x8 per-thread register tile.
// (Measured at the FFMA roofline — do not touch until tensor-core port.)
// ---------------------------------------------------------------------------
__global__ __launch_bounds__(256) void gcn_sgemm_kernel(
    const float* __restrict__ x,
    const float* __restrict__ w)
{
    const int BM = 128;
    const int BK = 16;

    __shared__ float As[BK][BM];     // x tile, transposed: As[k][m]
    __shared__ float Bs[BK][OUT_F];  // W tile: Bs[k][n]

    const int tid = threadIdx.x;
    const int block_row = blockIdx.x * BM;

    const int tx = tid & 15;   // 0..15 -> col group (8 cols each)
    const int ty = tid >> 4;   // 0..15 -> row group (8 rows each)

    const int a_row = tid >> 1;          // 0..127
    const int a_col = (tid & 1) * 8;     // 0 or 8

    const int b_row = tid >> 4;          // 0..15
    const int b_col = (tid & 15) * 8;    // 0..120

    float acc[8][8];
    #pragma unroll
    for (int i = 0; i < 8; i++)
        #pragma unroll
        for (int j = 0; j < 8; j++)
            acc[i][j] = 0.0f;

    const int g_arow = block_row + a_row;
    const bool a_valid = (g_arow < N_NODES);

    for (int kt = 0; kt < IN_F; kt += BK) {
        {
            float4 v0, v1;
            if (a_valid) {
                const float* xp = x + (size_t)g_arow * IN_F + kt + a_col;
                v0 = *(const float4*)(xp);
                v1 = *(const float4*)(xp + 4);
            } else {
                v0 = make_float4(0.f, 0.f, 0.f, 0.f);
                v1 = v0;
            }
            As[a_col + 0][a_row] = v0.x;
            As[a_col + 1][a_row] = v0.y;
            As[a_col + 2][a_row] = v0.z;
            As[a_col + 3][a_row] = v0.w;
            As[a_col + 4][a_row] = v1.x;
            As[a_col + 5][a_row] = v1.y;
            As[a_col + 6][a_row] = v1.z;
            As[a_col + 7][a_row] = v1.w;
        }
        {
            const float* wp = w + (size_t)(kt + b_row) * OUT_F + b_col;
            float4 v0 = *(const float4*)(wp);
            float4 v1 = *(const float4*)(wp + 4);
            *(float4*)(&Bs[b_row][b_col])     = v0;
            *(float4*)(&Bs[b_row][b_col + 4]) = v1;
        }
        __syncthreads();

        #pragma unroll
        for (int k = 0; k < BK; k++) {
            float a[8], b[8];
            float4 av0 = *(const float4*)(&As[k][ty * 8]);
            float4 av1 = *(const float4*)(&As[k][ty * 8 + 4]);
            float4 bv0 = *(const float4*)(&Bs[k][tx * 8]);
            float4 bv1 = *(const float4*)(&Bs[k][tx * 8 + 4]);
            a[0]=av0.x; a[1]=av0.y; a[2]=av0.z; a[3]=av0.w;
            a[4]=av1.x; a[5]=av1.y; a[6]=av1.z; a[7]=av1.w;
            b[0]=bv0.x; b[1]=bv0.y; b[2]=bv0.z; b[3]=bv0.w;
            b[4]=bv1.x; b[5]=bv1.y; b[6]=bv1.z; b[7]=bv1.w;
            #pragma unroll
            for (int i = 0; i < 8; i++)
                #pragma unroll
                for (int j = 0; j < 8; j++)
                    acc[i][j] = fmaf(a[i], b[j], acc[i][j]);
        }
        __syncthreads();
    }

    #pragma unroll
    for (int i = 0; i < 8; i++) {
        const int gr = block_row + ty * 8 + i;
        if (gr < N_NODES) {
            float* sp = g_support + (size_t)gr * OUT_F + tx * 8;
            float4 v0 = make_float4(acc[i][0], acc[i][1], acc[i][2], acc[i][3]);
            float4 v1 = make_float4(acc[i][4], acc[i][5], acc[i][6], acc[i][7]);
            *(float4*)(sp)     = v0;
            *(float4*)(sp + 4) = v1;
        }
    }
}

// ---------------------------------------------------------------------------
// Init out with broadcast bias: out[n, f] = bias[f]
// ---------------------------------------------------------------------------
__global__ void gcn_init_out_kernel(float* __restrict__ out,
                                    const float* __restrict__ bias)
{
    int i = blockIdx.x * blockDim.x + threadIdx.x;   // float4 index
    const int total4 = N_NODES * OUT_F / 4;
    if (i < total4) {
        const float4* b4 = (const float4*)bias;
        ((float4*)out)[i] = b4[i & (OUT_F / 4 - 1)];
    }
}

// ---------------------------------------------------------------------------
// Edge scatter: out[r] += val * support[c], one warp per edge.
// Lane l handles output features [4l, 4l+4) via ONE red.global.add.v4.f32.
// ---------------------------------------------------------------------------
__device__ __forceinline__ void red_add_v4(float* addr, float a, float b,
                                           float c, float d)
{
    asm volatile("red.global.add.v4.f32 [%0], {%1, %2, %3, %4};"
                 :: "l"(addr), "f"(a), "f"(b), "f"(c), "f"(d)
                 : "memory");
}

__global__ __launch_bounds__(256) void gcn_scatter_kernel(
    const int*   __restrict__ edge_rows,
    const int*   __restrict__ edge_cols,
    const float* __restrict__ edge_vals,
    float*       __restrict__ out)
{
    const int warp_id = (blockIdx.x * blockDim.x + threadIdx.x) >> 5;
    const int lane    = threadIdx.x & 31;
    if (warp_id >= N_EDGES) return;

    const int   r = __ldg(edge_rows + warp_id);
    const int   c = __ldg(edge_cols + warp_id);
    const float v = __ldg(edge_vals + warp_id);

    const float4 m = __ldg(((const float4*)(g_support + (size_t)c * OUT_F)) + lane);
    float* o = out + (size_t)r * OUT_F + lane * 4;
    red_add_v4(o, v * m.x, v * m.y, v * m.z, v * m.w);
}

// ---------------------------------------------------------------------------
// kernel_launch
// Inputs (metadata order): x, edge_rows, edge_cols, edge_vals, weight, bias
// ---------------------------------------------------------------------------
extern "C" void kernel_launch(void* const* d_in, const int* in_sizes, int n_in,
                              void* d_out, int out_size)
{
    const float* x         = (const float*)d_in[0];
    const int*   edge_rows = (const int*)  d_in[1];
    const int*   edge_cols = (const int*)  d_in[2];
    const float* edge_vals = (const float*)d_in[3];
    const float* weight    = (const float*)d_in[4];
    const float* bias      = (const float*)d_in[5];
    float*       out       = (float*)d_out;

    // 1) support = x @ W
    {
        dim3 grid((N_NODES + 127) / 128);
        gcn_sgemm_kernel<<<grid, 256>>>(x, weight);
    }
    // 2) out = bias (broadcast)
    {
        const int total4 = N_NODES * OUT_F / 4;
        gcn_init_out_kernel<<<(total4 + 255) / 256, 256>>>(out, bias);
    }
    // 3) out[r] += val * support[c] per edge
    {
        const int warps_per_block = 256 / 32;
        const int blocks = (N_EDGES + warps_per_block - 1) / warps_per_block;
        gcn_scatter_kernel<<<blocks, 256>>>(edge_rows, edge_cols, edge_vals, out);
    }
}

// round 3
// speedup vs baseline: 1.2326x; 1.2241x over previous
#include <cuda_runtime.h>

#define N_NODES 50000
#define N_EDGES 600000
#define IN_F    256
#define OUT_F   128

// Scratch (alloc-free rule: __device__ globals)
__device__ float g_support[(size_t)N_NODES * OUT_F];   // 25.6 MB
__device__ int   g_counts[N_NODES];
__device__ int   g_offsets[N_NODES + 1];
__device__ int   g_cursor[N_NODES];
__device__ int   g_sorted_cols[N_EDGES];
__device__ float g_sorted_vals[N_EDGES];

// ---------------------------------------------------------------------------
// SGEMM: support[M=50000, N=128] = x[M, K=256] @ W[K=256, N=128]
// 128x128 block tile, BK=16, 256 threads, 8x8 register tile. (FFMA roofline.)
// ---------------------------------------------------------------------------
__global__ __launch_bounds__(256) void gcn_sgemm_kernel(
    const float* __restrict__ x,
    const float* __restrict__ w)
{
    const int BM = 128;
    const int BK = 16;

    __shared__ float As[BK][BM];
    __shared__ float Bs[BK][OUT_F];

    const int tid = threadIdx.x;
    const int block_row = blockIdx.x * BM;

    const int tx = tid & 15;
    const int ty = tid >> 4;

    const int a_row = tid >> 1;
    const int a_col = (tid & 1) * 8;

    const int b_row = tid >> 4;
    const int b_col = (tid & 15) * 8;

    float acc[8][8];
    #pragma unroll
    for (int i = 0; i < 8; i++)
        #pragma unroll
        for (int j = 0; j < 8; j++)
            acc[i][j] = 0.0f;

    const int g_arow = block_row + a_row;
    const bool a_valid = (g_arow < N_NODES);

    for (int kt = 0; kt < IN_F; kt += BK) {
        {
            float4 v0, v1;
            if (a_valid) {
                const float* xp = x + (size_t)g_arow * IN_F + kt + a_col;
                v0 = *(const float4*)(xp);
                v1 = *(const float4*)(xp + 4);
            } else {
                v0 = make_float4(0.f, 0.f, 0.f, 0.f);
                v1 = v0;
            }
            As[a_col + 0][a_row] = v0.x;
            As[a_col + 1][a_row] = v0.y;
            As[a_col + 2][a_row] = v0.z;
            As[a_col + 3][a_row] = v0.w;
            As[a_col + 4][a_row] = v1.x;
            As[a_col + 5][a_row] = v1.y;
            As[a_col + 6][a_row] = v1.z;
            As[a_col + 7][a_row] = v1.w;
        }
        {
            const float* wp = w + (size_t)(kt + b_row) * OUT_F + b_col;
            float4 v0 = *(const float4*)(wp);
            float4 v1 = *(const float4*)(wp + 4);
            *(float4*)(&Bs[b_row][b_col])     = v0;
            *(float4*)(&Bs[b_row][b_col + 4]) = v1;
        }
        __syncthreads();

        #pragma unroll
        for (int k = 0; k < BK; k++) {
            float a[8], b[8];
            float4 av0 = *(const float4*)(&As[k][ty * 8]);
            float4 av1 = *(const float4*)(&As[k][ty * 8 + 4]);
            float4 bv0 = *(const float4*)(&Bs[k][tx * 8]);
            float4 bv1 = *(const float4*)(&Bs[k][tx * 8 + 4]);
            a[0]=av0.x; a[1]=av0.y; a[2]=av0.z; a[3]=av0.w;
            a[4]=av1.x; a[5]=av1.y; a[6]=av1.z; a[7]=av1.w;
            b[0]=bv0.x; b[1]=bv0.y; b[2]=bv0.z; b[3]=bv0.w;
            b[4]=bv1.x; b[5]=bv1.y; b[6]=bv1.z; b[7]=bv1.w;
            #pragma unroll
            for (int i = 0; i < 8; i++)
                #pragma unroll
                for (int j = 0; j < 8; j++)
                    acc[i][j] = fmaf(a[i], b[j], acc[i][j]);
        }
        __syncthreads();
    }

    #pragma unroll
    for (int i = 0; i < 8; i++) {
        const int gr = block_row + ty * 8 + i;
        if (gr < N_NODES) {
            float* sp = g_support + (size_t)gr * OUT_F + tx * 8;
            *(float4*)(sp)     = make_float4(acc[i][0], acc[i][1], acc[i][2], acc[i][3]);
            *(float4*)(sp + 4) = make_float4(acc[i][4], acc[i][5], acc[i][6], acc[i][7]);
        }
    }
}

// ---------------------------------------------------------------------------
// CSR build
// ---------------------------------------------------------------------------
__global__ void gcn_zero_counts_kernel()
{
    int i = blockIdx.x * blockDim.x + threadIdx.x;
    if (i < N_NODES) g_counts[i] = 0;
}

__global__ void gcn_histogram_kernel(const int* __restrict__ edge_rows)
{
    int e = blockIdx.x * blockDim.x + threadIdx.x;
    if (e < N_EDGES) atomicAdd(&g_counts[edge_rows[e]], 1);
}

// Single-block exclusive scan over g_counts -> g_offsets (and cursor copy).
__global__ __launch_bounds__(1024) void gcn_scan_kernel()
{
    __shared__ int sdata[1024];
    __shared__ int s_carry;
    if (threadIdx.x == 0) s_carry = 0;
    __syncthreads();

    for (int base = 0; base < N_NODES; base += 1024) {
        int i = base + threadIdx.x;
        int v = (i < N_NODES) ? g_counts[i] : 0;
        sdata[threadIdx.x] = v;
        __syncthreads();
        // Hillis-Steele inclusive scan
        #pragma unroll
        for (int off = 1; off < 1024; off <<= 1) {
            int t = (threadIdx.x >= off) ? sdata[threadIdx.x - off] : 0;
            __syncthreads();
            sdata[threadIdx.x] += t;
            __syncthreads();
        }
        int incl = sdata[threadIdx.x];
        int excl = incl - v;
        if (i < N_NODES) {
            int o = s_carry + excl;
            g_offsets[i] = o;
            g_cursor[i]  = o;
        }
        __syncthreads();
        if (threadIdx.x == 0) s_carry += sdata[1023];
        __syncthreads();
    }
    if (threadIdx.x == 0) g_offsets[N_NODES] = s_carry;
}

__global__ void gcn_permute_kernel(const int*   __restrict__ edge_rows,
                                   const int*   __restrict__ edge_cols,
                                   const float* __restrict__ edge_vals)
{
    int e = blockIdx.x * blockDim.x + threadIdx.x;
    if (e < N_EDGES) {
        int r = edge_rows[e];
        int pos = atomicAdd(&g_cursor[r], 1);
        g_sorted_cols[pos] = edge_cols[e];
        g_sorted_vals[pos] = edge_vals[e];
    }
}

// ---------------------------------------------------------------------------
// Aggregate: one warp per node. Lane l owns features [4l, 4l+4).
// out[r] = bias + sum_{e in CSR[r]} val[e] * support[col[e]]
// ---------------------------------------------------------------------------
__global__ __launch_bounds__(256) void gcn_aggregate_kernel(
    float* __restrict__ out,
    const float* __restrict__ bias)
{
    const int warp_id = (blockIdx.x * blockDim.x + threadIdx.x) >> 5;
    const int lane    = threadIdx.x & 31;
    if (warp_id >= N_NODES) return;

    const int start = g_offsets[warp_id];
    const int end   = g_offsets[warp_id + 1];

    float4 acc = make_float4(0.f, 0.f, 0.f, 0.f);

    for (int base = start; base < end; base += 32) {
        const int n = min(32, end - base);
        int   c = 0;
        float v = 0.f;
        if (lane < n) {
            c = __ldg(g_sorted_cols + base + lane);
            v = __ldg(g_sorted_vals + base + lane);
        }
        for (int j = 0; j < n; j++) {
            const int   cj = __shfl_sync(0xffffffffu, c, j);
            const float vj = __shfl_sync(0xffffffffu, v, j);
            const float4 m = __ldg(((const float4*)g_support) + (size_t)cj * 32 + lane);
            acc.x = fmaf(vj, m.x, acc.x);
            acc.y = fmaf(vj, m.y, acc.y);
            acc.z = fmaf(vj, m.z, acc.z);
            acc.w = fmaf(vj, m.w, acc.w);
        }
    }

    const float4 b = __ldg(((const float4*)bias) + lane);
    acc.x += b.x; acc.y += b.y; acc.z += b.z; acc.w += b.w;
    ((float4*)out)[(size_t)warp_id * 32 + lane] = acc;
}

// ---------------------------------------------------------------------------
// kernel_launch
// Inputs (metadata order): x, edge_rows, edge_cols, edge_vals, weight, bias
// ---------------------------------------------------------------------------
extern "C" void kernel_launch(void* const* d_in, const int* in_sizes, int n_in,
                              void* d_out, int out_size)
{
    const float* x         = (const float*)d_in[0];
    const int*   edge_rows = (const int*)  d_in[1];
    const int*   edge_cols = (const int*)  d_in[2];
    const float* edge_vals = (const float*)d_in[3];
    const float* weight    = (const float*)d_in[4];
    const float* bias      = (const float*)d_in[5];
    float*       out       = (float*)d_out;

    // 1) support = x @ W
    gcn_sgemm_kernel<<<(N_NODES + 127) / 128, 256>>>(x, weight);

    // 2) CSR build
    gcn_zero_counts_kernel<<<(N_NODES + 255) / 256, 256>>>();
    gcn_histogram_kernel<<<(N_EDGES + 255) / 256, 256>>>(edge_rows);
    gcn_scan_kernel<<<1, 1024>>>();
    gcn_permute_kernel<<<(N_EDGES + 255) / 256, 256>>>(edge_rows, edge_cols, edge_vals);

    // 3) aggregate + bias (no atomics, no init pass)
    {
        const int warps_per_block = 256 / 32;
        const int blocks = (N_NODES + warps_per_block - 1) / warps_per_block;
        gcn_aggregate_kernel<<<blocks, 256>>>(out, bias);
    }
}

// round 4
// speedup vs baseline: 1.7401x; 1.4118x over previous
#include <cuda_runtime.h>

#define N_NODES 50000
#define N_EDGES 600000
#define IN_F    256
#define OUT_F   128

#define SCAN_CHUNK   1024
#define NUM_CHUNKS   ((N_NODES + SCAN_CHUNK - 1) / SCAN_CHUNK)   // 49

// Scratch (alloc-free rule: __device__ globals)
__device__ float g_support[(size_t)N_NODES * OUT_F];   // 25.6 MB
__device__ int   g_counts[N_NODES];
__device__ int   g_offsets[N_NODES + 1];
__device__ int   g_cursor[N_NODES];
__device__ int   g_partials[NUM_CHUNKS];
__device__ int   g_chunk_base[NUM_CHUNKS];
__device__ int   g_sorted_cols[N_EDGES];
__device__ float g_sorted_vals[N_EDGES];

// ---------------------------------------------------------------------------
// SGEMM: support[M=50000, N=128] = x[M, K=256] @ W[K=256, N=128]
// 128x128 block tile, BK=16, 256 threads, 8x8 register tile. (FFMA roofline.)
// ---------------------------------------------------------------------------
__global__ __launch_bounds__(256) void gcn_sgemm_kernel(
    const float* __restrict__ x,
    const float* __restrict__ w)
{
    const int BM = 128;
    const int BK = 16;

    __shared__ float As[BK][BM];
    __shared__ float Bs[BK][OUT_F];

    const int tid = threadIdx.x;
    const int block_row = blockIdx.x * BM;

    const int tx = tid & 15;
    const int ty = tid >> 4;

    const int a_row = tid >> 1;
    const int a_col = (tid & 1) * 8;

    const int b_row = tid >> 4;
    const int b_col = (tid & 15) * 8;

    float acc[8][8];
    #pragma unroll
    for (int i = 0; i < 8; i++)
        #pragma unroll
        for (int j = 0; j < 8; j++)
            acc[i][j] = 0.0f;

    const int g_arow = block_row + a_row;
    const bool a_valid = (g_arow < N_NODES);

    for (int kt = 0; kt < IN_F; kt += BK) {
        {
            float4 v0, v1;
            if (a_valid) {
                const float* xp = x + (size_t)g_arow * IN_F + kt + a_col;
                v0 = *(const float4*)(xp);
                v1 = *(const float4*)(xp + 4);
            } else {
                v0 = make_float4(0.f, 0.f, 0.f, 0.f);
                v1 = v0;
            }
            As[a_col + 0][a_row] = v0.x;
            As[a_col + 1][a_row] = v0.y;
            As[a_col + 2][a_row] = v0.z;
            As[a_col + 3][a_row] = v0.w;
            As[a_col + 4][a_row] = v1.x;
            As[a_col + 5][a_row] = v1.y;
            As[a_col + 6][a_row] = v1.z;
            As[a_col + 7][a_row] = v1.w;
        }
        {
            const float* wp = w + (size_t)(kt + b_row) * OUT_F + b_col;
            float4 v0 = *(const float4*)(wp);
            float4 v1 = *(const float4*)(wp + 4);
            *(float4*)(&Bs[b_row][b_col])     = v0;
            *(float4*)(&Bs[b_row][b_col + 4]) = v1;
        }
        __syncthreads();

        #pragma unroll
        for (int k = 0; k < BK; k++) {
            float a[8], b[8];
            float4 av0 = *(const float4*)(&As[k][ty * 8]);
            float4 av1 = *(const float4*)(&As[k][ty * 8 + 4]);
            float4 bv0 = *(const float4*)(&Bs[k][tx * 8]);
            float4 bv1 = *(const float4*)(&Bs[k][tx * 8 + 4]);
            a[0]=av0.x; a[1]=av0.y; a[2]=av0.z; a[3]=av0.w;
            a[4]=av1.x; a[5]=av1.y; a[6]=av1.z; a[7]=av1.w;
            b[0]=bv0.x; b[1]=bv0.y; b[2]=bv0.z; b[3]=bv0.w;
            b[4]=bv1.x; b[5]=bv1.y; b[6]=bv1.z; b[7]=bv1.w;
            #pragma unroll
            for (int i = 0; i < 8; i++)
                #pragma unroll
                for (int j = 0; j < 8; j++)
                    acc[i][j] = fmaf(a[i], b[j], acc[i][j]);
        }
        __syncthreads();
    }

    #pragma unroll
    for (int i = 0; i < 8; i++) {
        const int gr = block_row + ty * 8 + i;
        if (gr < N_NODES) {
            float* sp = g_support + (size_t)gr * OUT_F + tx * 8;
            *(float4*)(sp)     = make_float4(acc[i][0], acc[i][1], acc[i][2], acc[i][3]);
            *(float4*)(sp + 4) = make_float4(acc[i][4], acc[i][5], acc[i][6], acc[i][7]);
        }
    }
}

// ---------------------------------------------------------------------------
// CSR build
// ---------------------------------------------------------------------------
__global__ void gcn_zero_counts_kernel()
{
    int i = blockIdx.x * blockDim.x + threadIdx.x;
    if (i < N_NODES) g_counts[i] = 0;
}

__global__ void gcn_histogram_kernel(const int* __restrict__ edge_rows)
{
    int e = blockIdx.x * blockDim.x + threadIdx.x;
    if (e < N_EDGES) atomicAdd(&g_counts[edge_rows[e]], 1);
}

// Phase 1: per-chunk sums. grid=NUM_CHUNKS, block=1024.
__global__ __launch_bounds__(1024) void gcn_scan_reduce_kernel()
{
    __shared__ int sdata[32];
    const int i = blockIdx.x * SCAN_CHUNK + threadIdx.x;
    int v = (i < N_NODES) ? g_counts[i] : 0;

    // warp reduce
    #pragma unroll
    for (int off = 16; off > 0; off >>= 1)
        v += __shfl_down_sync(0xffffffffu, v, off);
    if ((threadIdx.x & 31) == 0) sdata[threadIdx.x >> 5] = v;
    __syncthreads();
    if (threadIdx.x < 32) {
        int w = sdata[threadIdx.x];
        #pragma unroll
        for (int off = 16; off > 0; off >>= 1)
            w += __shfl_down_sync(0xffffffffu, w, off);
        if (threadIdx.x == 0) g_partials[blockIdx.x] = w;
    }
}

// Phase 2: exclusive scan of NUM_CHUNKS (<=64) partials by one warp chain.
__global__ void gcn_scan_partials_kernel()
{
    // single block, 64 threads, simple shared-memory scan
    __shared__ int s[64];
    int v = (threadIdx.x < NUM_CHUNKS) ? g_partials[threadIdx.x] : 0;
    s[threadIdx.x] = v;
    __syncthreads();
    #pragma unroll
    for (int off = 1; off < 64; off <<= 1) {
        int t = (threadIdx.x >= off) ? s[threadIdx.x - off] : 0;
        __syncthreads();
        s[threadIdx.x] += t;
        __syncthreads();
    }
    if (threadIdx.x < NUM_CHUNKS) g_chunk_base[threadIdx.x] = s[threadIdx.x] - v;
    if (threadIdx.x == 63) g_offsets[N_NODES] = s[63];
}

// Phase 3: per-chunk exclusive scan + base. grid=NUM_CHUNKS, block=1024.
__global__ __launch_bounds__(1024) void gcn_scan_final_kernel()
{
    __shared__ int warp_sums[32];
    const int i = blockIdx.x * SCAN_CHUNK + threadIdx.x;
    const int lane = threadIdx.x & 31;
    const int warp = threadIdx.x >> 5;

    int v = (i < N_NODES) ? g_counts[i] : 0;

    // warp inclusive scan
    int incl = v;
    #pragma unroll
    for (int off = 1; off < 32; off <<= 1) {
        int t = __shfl_up_sync(0xffffffffu, incl, off);
        if (lane >= off) incl += t;
    }
    if (lane == 31) warp_sums[warp] = incl;
    __syncthreads();
    if (warp == 0) {
        int w = (lane < 32) ? warp_sums[lane] : 0;
        int wi = w;
        #pragma unroll
        for (int off = 1; off < 32; off <<= 1) {
            int t = __shfl_up_sync(0xffffffffu, wi, off);
            if (lane >= off) wi += t;
        }
        warp_sums[lane] = wi - w;   // exclusive
    }
    __syncthreads();

    if (i < N_NODES) {
        int o = g_chunk_base[blockIdx.x] + warp_sums[warp] + (incl - v);
        g_offsets[i] = o;
        g_cursor[i]  = o;
    }
}

__global__ void gcn_permute_kernel(const int*   __restrict__ edge_rows,
                                   const int*   __restrict__ edge_cols,
                                   const float* __restrict__ edge_vals)
{
    int e = blockIdx.x * blockDim.x + threadIdx.x;
    if (e < N_EDGES) {
        int r = edge_rows[e];
        int pos = atomicAdd(&g_cursor[r], 1);
        g_sorted_cols[pos] = edge_cols[e];
        g_sorted_vals[pos] = edge_vals[e];
    }
}

// ---------------------------------------------------------------------------
// Aggregate: one warp per node. Lane l owns features [4l, 4l+4).
// out[r] = bias + sum_{e in CSR[r]} val[e] * support[col[e]]
// ---------------------------------------------------------------------------
__global__ __launch_bounds__(256) void gcn_aggregate_kernel(
    float* __restrict__ out,
    const float* __restrict__ bias)
{
    const int warp_id = (blockIdx.x * blockDim.x + threadIdx.x) >> 5;
    const int lane    = threadIdx.x & 31;
    if (warp_id >= N_NODES) return;

    const int start = g_offsets[warp_id];
    const int end   = g_offsets[warp_id + 1];

    float4 acc = make_float4(0.f, 0.f, 0.f, 0.f);

    for (int base = start; base < end; base += 32) {
        const int n = min(32, end - base);
        int   c = 0;
        float v = 0.f;
        if (lane < n) {
            c = __ldg(g_sorted_cols + base + lane);
            v = __ldg(g_sorted_vals + base + lane);
        }
        for (int j = 0; j < n; j++) {
            const int   cj = __shfl_sync(0xffffffffu, c, j);
            const float vj = __shfl_sync(0xffffffffu, v, j);
            const float4 m = __ldg(((const float4*)g_support) + (size_t)cj * 32 + lane);
            acc.x = fmaf(vj, m.x, acc.x);
            acc.y = fmaf(vj, m.y, acc.y);
            acc.z = fmaf(vj, m.z, acc.z);
            acc.w = fmaf(vj, m.w, acc.w);
        }
    }

    const float4 b = __ldg(((const float4*)bias) + lane);
    acc.x += b.x; acc.y += b.y; acc.z += b.z; acc.w += b.w;
    ((float4*)out)[(size_t)warp_id * 32 + lane] = acc;
}

// ---------------------------------------------------------------------------
// kernel_launch
// Inputs (metadata order): x, edge_rows, edge_cols, edge_vals, weight, bias
// ---------------------------------------------------------------------------
extern "C" void kernel_launch(void* const* d_in, const int* in_sizes, int n_in,
                              void* d_out, int out_size)
{
    const float* x         = (const float*)d_in[0];
    const int*   edge_rows = (const int*)  d_in[1];
    const int*   edge_cols = (const int*)  d_in[2];
    const float* edge_vals = (const float*)d_in[3];
    const float* weight    = (const float*)d_in[4];
    const float* bias      = (const float*)d_in[5];
    float*       out       = (float*)d_out;

    // 1) support = x @ W
    gcn_sgemm_kernel<<<(N_NODES + 127) / 128, 256>>>(x, weight);

    // 2) CSR build
    gcn_zero_counts_kernel<<<(N_NODES + 255) / 256, 256>>>();
    gcn_histogram_kernel<<<(N_EDGES + 255) / 256, 256>>>(edge_rows);
    gcn_scan_reduce_kernel<<<NUM_CHUNKS, 1024>>>();
    gcn_scan_partials_kernel<<<1, 64>>>();
    gcn_scan_final_kernel<<<NUM_CHUNKS, 1024>>>();
    gcn_permute_kernel<<<(N_EDGES + 255) / 256, 256>>>(edge_rows, edge_cols, edge_vals);

    // 3) aggregate + bias (no atomics, no init pass)
    {
        const int warps_per_block = 256 / 32;
        const int blocks = (N_NODES + warps_per_block - 1) / warps_per_block;
        gcn_aggregate_kernel<<<blocks, 256>>>(out, bias);
    }
}

// round 6
// speedup vs baseline: 2.1330x; 1.2258x over previous
#include <cuda_runtime.h>
#include <cstdint>

#define N_NODES 50000
#define N_EDGES 600000
#define IN_F    256
#define OUT_F   128

#define SCAN_CHUNK   1024
#define NUM_CHUNKS   ((N_NODES + SCAN_CHUNK - 1) / SCAN_CHUNK)   // 49

// Scratch (alloc-free rule: __device__ globals)
__device__ float g_support[(size_t)N_NODES * OUT_F];   // 25.6 MB
__device__ int   g_counts[N_NODES];
__device__ int   g_offsets[N_NODES + 1];
__device__ int   g_cursor[N_NODES];
__device__ int   g_partials[NUM_CHUNKS];
__device__ int   g_chunk_base[NUM_CHUNKS];
__device__ int   g_sorted_cols[N_EDGES];
__device__ float g_sorted_vals[N_EDGES];

// Arch-specific gate: tcgen05 only exists in the sm_103a (arch-specific) pass.
// The harness also runs a compute_103 (family) ptxas pass, which must see the
// FFMA fallback instead.
#if defined(__CUDA_ARCH__) && (__CUDA_ARCH__ == 1030) && \
    (defined(__CUDA_ARCH_FEAT_SM103_ALL) || defined(__CUDA_ARCH_SPECIFIC__))
#define GCN_HAS_TCGEN05 1
#else
#define GCN_HAS_TCGEN05 0
#endif

// ===========================================================================
// GEMM: support[50000,128] = x[50000,256] @ W[256,128]
// sm_103a path: tcgen05 kind::tf32, 3xTF32 decomposition, SS-mode.
// family path:  FFMA register-tiled SGEMM (round-1 proven code).
// Both paths: grid = ceil(M/128), 256 threads, dynamic SMEM.
// ===========================================================================

#define K_CHUNK     64
#define NUM_KCHUNK  (IN_F / K_CHUNK)       // 4
#define TILE_BYTES  (128 * K_CHUNK * 4)    // 32768 per tile version

#define SM_TMEM_PTR 0
#define SM_MBAR     8
#define SM_A_BIG    1024
#define SM_A_SMALL  (SM_A_BIG   + TILE_BYTES)
#define SM_B_BIG    (SM_A_SMALL + TILE_BYTES)
#define SM_B_SMALL  (SM_B_BIG   + TILE_BYTES)
#define SM_TOTAL    (SM_B_SMALL + TILE_BYTES)   // 132096

// idesc kind::tf32: dtype=F32(1)<<4, atype=TF32(2)<<7, btype=TF32(2)<<10,
// (N/8)<<17, (M/16)<<24  -> M=128, N=128
#define TF32_IDESC  0x8200910u

// SMEM descriptor: SW128 K-major, version=1, SBO=64 (1024B groups), LBO=1
#define DESC_BASE   0x4000404000010000ull
#define MAKE_DESC(a) (DESC_BASE | (uint64_t)(((a) >> 4) & 0x3FFF))

__device__ __forceinline__ uint32_t smem_u32(const void* p) {
    uint32_t a;
    asm("{ .reg .u64 t; cvta.to.shared.u64 t, %1; cvt.u32.u64 %0, t; }"
        : "=r"(a) : "l"(p));
    return a;
}

#if GCN_HAS_TCGEN05
__device__ __forceinline__ uint32_t tf32_rna(float a) {
    uint32_t r;
    asm("cvt.rna.tf32.f32 %0, %1;" : "=r"(r) : "f"(a));
    return r;
}

__device__ __forceinline__ uint32_t elect_one() {
    uint32_t p;
    asm volatile("{ .reg .pred p; elect.sync _|p, 0xFFFFFFFF; selp.b32 %0,1,0,p; }"
                 : "=r"(p));
    return p;
}

__device__ __forceinline__ void mma_tf32_ss(uint32_t d_tmem, uint64_t a_desc,
                                            uint64_t b_desc, uint32_t idesc,
                                            uint32_t enable_d) {
    asm volatile(
        "{\n\t.reg .pred p;\n\tsetp.ne.u32 p, %4, 0;\n\t"
        "tcgen05.mma.cta_group::1.kind::tf32 [%0], %1, %2, %3, {%5,%5,%5,%5}, p;\n\t}"
        :: "r"(d_tmem), "l"(a_desc), "l"(b_desc), "r"(idesc),
           "r"(enable_d), "r"(0u)
        : "memory");
}

__device__ __forceinline__ uint32_t swz(uint32_t b) {
    return b ^ ((b >> 3) & 0x70);
}

// blocked SW128 atom byte offset for element (row, col) in a 128 x K_CHUNK f32 tile
__device__ __forceinline__ uint32_t tile_off(int row, int col) {
    uint32_t byte = (uint32_t)(((row >> 3) + (col >> 5) * 16) * 1024
                               + (row & 7) * 128 + (col & 31) * 4);
    return swz(byte);
}
#endif  // GCN_HAS_TCGEN05

__global__ __launch_bounds__(256) void gcn_gemm_tc_kernel(
    const float* __restrict__ x,
    const float* __restrict__ w)
{
    extern __shared__ char smem[];
    const int tid  = threadIdx.x;
    const int block_row = blockIdx.x * 128;

#if GCN_HAS_TCGEN05
    // ---------------- tcgen05 TF32x3 path (sm_103a) ----------------
    const uint32_t sbase = smem_u32(smem);
    const int wid  = tid >> 5;
    const int lane = tid & 31;

    if (wid == 0) {
        asm volatile("tcgen05.alloc.cta_group::1.sync.aligned.shared::cta.b32 [%0], %1;"
                     :: "r"(sbase + SM_TMEM_PTR), "r"(128u) : "memory");
        asm volatile("tcgen05.relinquish_alloc_permit.cta_group::1.sync.aligned;");
    }
    if (tid == 0) {
        asm volatile("mbarrier.init.shared.b64 [%0], %1;"
                     :: "r"(sbase + SM_MBAR), "r"(1u) : "memory");
    }
    __syncthreads();

    uint32_t tmem;
    asm volatile("ld.shared.b32 %0, [%1];" : "=r"(tmem) : "r"(sbase + SM_TMEM_PTR));

    for (int kc = 0; kc < NUM_KCHUNK; kc++) {
        const int kb = kc * K_CHUNK;

        // A chunk: x[block_row..+128, kb..+64], split big/small
        for (int i = tid; i < 128 * (K_CHUNK / 4); i += 256) {
            const int row = i >> 4;
            const int c4  = (i & 15) * 4;
            const int gr  = block_row + row;
            float4 v = make_float4(0.f, 0.f, 0.f, 0.f);
            if (gr < N_NODES)
                v = *(const float4*)(x + (size_t)gr * IN_F + kb + c4);
            uint32_t bx = tf32_rna(v.x), by = tf32_rna(v.y),
                     bz = tf32_rna(v.z), bw = tf32_rna(v.w);
            float sx = v.x - __uint_as_float(bx);
            float sy = v.y - __uint_as_float(by);
            float sz = v.z - __uint_as_float(bz);
            float sw = v.w - __uint_as_float(bw);
            const uint32_t o = tile_off(row, c4);
            *(uint4*)(smem + SM_A_BIG + o)    = make_uint4(bx, by, bz, bw);
            *(float4*)(smem + SM_A_SMALL + o) = make_float4(sx, sy, sz, sw);
        }
        // B chunk transposed: B_sm[n][k] = W[kb+k][n]
        for (int i = tid; i < K_CHUNK * OUT_F; i += 256) {
            const int kl = i >> 7;
            const int n  = i & 127;
            const float v = __ldg(w + (size_t)(kb + kl) * OUT_F + n);
            const uint32_t b = tf32_rna(v);
            const float s = v - __uint_as_float(b);
            const uint32_t o = tile_off(n, kl);
            *(uint32_t*)(smem + SM_B_BIG + o) = b;
            *(float*)(smem + SM_B_SMALL + o)  = s;
        }
        asm volatile("fence.proxy.async.shared::cta;" ::: "memory");
        __syncthreads();

        if (wid == 0 && elect_one()) {
            const uint64_t ab = MAKE_DESC(sbase + SM_A_BIG);
            const uint64_t as = MAKE_DESC(sbase + SM_A_SMALL);
            const uint64_t bb = MAKE_DESC(sbase + SM_B_BIG);
            const uint64_t bs = MAKE_DESC(sbase + SM_B_SMALL);
            #pragma unroll
            for (int s = 0; s < K_CHUNK / 8; s++) {   // 8 k-steps of K=8
                const uint64_t off = (uint64_t)((s >> 2) * 1024 + (s & 3) * 2);
                const uint32_t first = (kc == 0 && s == 0) ? 0u : 1u;
                mma_tf32_ss(tmem, ab + off, bb + off, TF32_IDESC, first);
                mma_tf32_ss(tmem, as + off, bb + off, TF32_IDESC, 1u);
                mma_tf32_ss(tmem, ab + off, bs + off, TF32_IDESC, 1u);
            }
            asm volatile(
                "tcgen05.commit.cta_group::1.mbarrier::arrive::one.shared::cluster.b64 [%0];"
                :: "r"(sbase + SM_MBAR) : "memory");
        }

        // wait for this chunk's MMAs before SMEM reuse
        {
            const uint32_t parity = (uint32_t)(kc & 1);
            uint32_t done;
            asm volatile(
                "{\n\t.reg .pred p;\n\t"
                "mbarrier.try_wait.parity.acquire.cta.shared::cta.b64 p, [%1], %2;\n\t"
                "selp.b32 %0, 1, 0, p;\n\t}"
                : "=r"(done) : "r"(sbase + SM_MBAR), "r"(parity) : "memory");
            while (!done) {
                asm volatile(
                    "{\n\t.reg .pred p;\n\t"
                    "mbarrier.try_wait.parity.acquire.cta.shared::cta.b64 p, [%1], %2, 0x989680;\n\t"
                    "selp.b32 %0, 1, 0, p;\n\t}"
                    : "=r"(done) : "r"(sbase + SM_MBAR), "r"(parity) : "memory");
            }
        }
    }

    asm volatile("tcgen05.fence::after_thread_sync;" ::: "memory");

    // epilogue: 8 warps read D from TMEM, store to g_support
    {
        const int sub  = wid & 3;
        const int half = wid >> 2;
        uint32_t d[64];
        const uint32_t taddr = tmem + half * 64;
        asm volatile(
            "tcgen05.ld.sync.aligned.32x32b.x32.b32 "
            "{%0,%1,%2,%3,%4,%5,%6,%7,%8,%9,%10,%11,%12,%13,%14,%15,"
            "%16,%17,%18,%19,%20,%21,%22,%23,%24,%25,%26,%27,%28,%29,%30,%31}, [%32];"
            : "=r"(d[0]),"=r"(d[1]),"=r"(d[2]),"=r"(d[3]),"=r"(d[4]),"=r"(d[5]),"=r"(d[6]),"=r"(d[7]),
              "=r"(d[8]),"=r"(d[9]),"=r"(d[10]),"=r"(d[11]),"=r"(d[12]),"=r"(d[13]),"=r"(d[14]),"=r"(d[15]),
              "=r"(d[16]),"=r"(d[17]),"=r"(d[18]),"=r"(d[19]),"=r"(d[20]),"=r"(d[21]),"=r"(d[22]),"=r"(d[23]),
              "=r"(d[24]),"=r"(d[25]),"=r"(d[26]),"=r"(d[27]),"=r"(d[28]),"=r"(d[29]),"=r"(d[30]),"=r"(d[31])
            : "r"(taddr));
        asm volatile(
            "tcgen05.ld.sync.aligned.32x32b.x32.b32 "
            "{%0,%1,%2,%3,%4,%5,%6,%7,%8,%9,%10,%11,%12,%13,%14,%15,"
            "%16,%17,%18,%19,%20,%21,%22,%23,%24,%25,%26,%27,%28,%29,%30,%31}, [%32];"
            : "=r"(d[32]),"=r"(d[33]),"=r"(d[34]),"=r"(d[35]),"=r"(d[36]),"=r"(d[37]),"=r"(d[38]),"=r"(d[39]),
              "=r"(d[40]),"=r"(d[41]),"=r"(d[42]),"=r"(d[43]),"=r"(d[44]),"=r"(d[45]),"=r"(d[46]),"=r"(d[47]),
              "=r"(d[48]),"=r"(d[49]),"=r"(d[50]),"=r"(d[51]),"=r"(d[52]),"=r"(d[53]),"=r"(d[54]),"=r"(d[55]),
              "=r"(d[56]),"=r"(d[57]),"=r"(d[58]),"=r"(d[59]),"=r"(d[60]),"=r"(d[61]),"=r"(d[62]),"=r"(d[63])
            : "r"(taddr + 32));
        asm volatile("tcgen05.wait::ld.sync.aligned;" ::: "memory");

        const int gr = block_row + sub * 32 + lane;
        if (gr < N_NODES) {
            float* sp = g_support + (size_t)gr * OUT_F + half * 64;
            #pragma unroll
            for (int q = 0; q < 16; q++) {
                *(float4*)(sp + q * 4) = make_float4(
                    __uint_as_float(d[q * 4 + 0]), __uint_as_float(d[q * 4 + 1]),
                    __uint_as_float(d[q * 4 + 2]), __uint_as_float(d[q * 4 + 3]));
            }
        }
    }

    __syncthreads();
    if (tid == 0) {
        asm volatile("mbarrier.inval.shared.b64 [%0];" :: "r"(sbase + SM_MBAR) : "memory");
    }
    if (wid == 0) {
        asm volatile("tcgen05.dealloc.cta_group::1.sync.aligned.b32 %0, %1;"
                     :: "r"(tmem), "r"(128u));
    }

#else
    // ---------------- FFMA fallback (family compute_103 pass) ----------------
    const int BK = 16;
    float* As = (float*)smem;                 // [BK][128]
    float* Bs = As + BK * 128;                // [BK][128]

    const int tx = tid & 15;
    const int ty = tid >> 4;
    const int a_row = tid >> 1;
    const int a_col = (tid & 1) * 8;
    const int b_row = tid >> 4;
    const int b_col = (tid & 15) * 8;

    float acc[8][8];
    #pragma unroll
    for (int i = 0; i < 8; i++)
        #pragma unroll
        for (int j = 0; j < 8; j++)
            acc[i][j] = 0.0f;

    const int g_arow = block_row + a_row;
    const bool a_valid = (g_arow < N_NODES);

    for (int kt = 0; kt < IN_F; kt += BK) {
        {
            float4 v0, v1;
            if (a_valid) {
                const float* xp = x + (size_t)g_arow * IN_F + kt + a_col;
                v0 = *(const float4*)(xp);
                v1 = *(const float4*)(xp + 4);
            } else {
                v0 = make_float4(0.f, 0.f, 0.f, 0.f);
                v1 = v0;
            }
            As[(a_col + 0) * 128 + a_row] = v0.x;
            As[(a_col + 1) * 128 + a_row] = v0.y;
            As[(a_col + 2) * 128 + a_row] = v0.z;
            As[(a_col + 3) * 128 + a_row] = v0.w;
            As[(a_col + 4) * 128 + a_row] = v1.x;
            As[(a_col + 5) * 128 + a_row] = v1.y;
            As[(a_col + 6) * 128 + a_row] = v1.z;
            As[(a_col + 7) * 128 + a_row] = v1.w;
        }
        {
            const float* wp = w + (size_t)(kt + b_row) * OUT_F + b_col;
            float4 v0 = *(const float4*)(wp);
            float4 v1 = *(const float4*)(wp + 4);
            *(float4*)(&Bs[b_row * 128 + b_col])     = v0;
            *(float4*)(&Bs[b_row * 128 + b_col + 4]) = v1;
        }
        __syncthreads();

        #pragma unroll
        for (int k = 0; k < BK; k++) {
            float a[8], b[8];
            float4 av0 = *(const float4*)(&As[k * 128 + ty * 8]);
            float4 av1 = *(const float4*)(&As[k * 128 + ty * 8 + 4]);
            float4 bv0 = *(const float4*)(&Bs[k * 128 + tx * 8]);
            float4 bv1 = *(const float4*)(&Bs[k * 128 + tx * 8 + 4]);
            a[0]=av0.x; a[1]=av0.y; a[2]=av0.z; a[3]=av0.w;
            a[4]=av1.x; a[5]=av1.y; a[6]=av1.z; a[7]=av1.w;
            b[0]=bv0.x; b[1]=bv0.y; b[2]=bv0.z; b[3]=bv0.w;
            b[4]=bv1.x; b[5]=bv1.y; b[6]=bv1.z; b[7]=bv1.w;
            #pragma unroll
            for (int i = 0; i < 8; i++)
                #pragma unroll
                for (int j = 0; j < 8; j++)
                    acc[i][j] = fmaf(a[i], b[j], acc[i][j]);
        }
        __syncthreads();
    }

    #pragma unroll
    for (int i = 0; i < 8; i++) {
        const int gr = block_row + ty * 8 + i;
        if (gr < N_NODES) {
            float* sp = g_support + (size_t)gr * OUT_F + tx * 8;
            *(float4*)(sp)     = make_float4(acc[i][0], acc[i][1], acc[i][2], acc[i][3]);
            *(float4*)(sp + 4) = make_float4(acc[i][4], acc[i][5], acc[i][6], acc[i][7]);
        }
    }
#endif
}

// ---------------------------------------------------------------------------
// CSR build
// ---------------------------------------------------------------------------
__global__ void gcn_zero_counts_kernel()
{
    int i = blockIdx.x * blockDim.x + threadIdx.x;
    if (i < N_NODES) g_counts[i] = 0;
}

__global__ void gcn_histogram_kernel(const int* __restrict__ edge_rows)
{
    int e = blockIdx.x * blockDim.x + threadIdx.x;
    if (e < N_EDGES) atomicAdd(&g_counts[edge_rows[e]], 1);
}

__global__ __launch_bounds__(1024) void gcn_scan_reduce_kernel()
{
    __shared__ int sdata[32];
    const int i = blockIdx.x * SCAN_CHUNK + threadIdx.x;
    int v = (i < N_NODES) ? g_counts[i] : 0;
    #pragma unroll
    for (int off = 16; off > 0; off >>= 1)
        v += __shfl_down_sync(0xffffffffu, v, off);
    if ((threadIdx.x & 31) == 0) sdata[threadIdx.x >> 5] = v;
    __syncthreads();
    if (threadIdx.x < 32) {
        int w = sdata[threadIdx.x];
        #pragma unroll
        for (int off = 16; off > 0; off >>= 1)
            w += __shfl_down_sync(0xffffffffu, w, off);
        if (threadIdx.x == 0) g_partials[blockIdx.x] = w;
    }
}

__global__ void gcn_scan_partials_kernel()
{
    __shared__ int s[64];
    int v = (threadIdx.x < NUM_CHUNKS) ? g_partials[threadIdx.x] : 0;
    s[threadIdx.x] = v;
    __syncthreads();
    #pragma unroll
    for (int off = 1; off < 64; off <<= 1) {
        int t = (threadIdx.x >= off) ? s[threadIdx.x - off] : 0;
        __syncthreads();
        s[threadIdx.x] += t;
        __syncthreads();
    }
    if (threadIdx.x < NUM_CHUNKS) g_chunk_base[threadIdx.x] = s[threadIdx.x] - v;
    if (threadIdx.x == 63) g_offsets[N_NODES] = s[63];
}

__global__ __launch_bounds__(1024) void gcn_scan_final_kernel()
{
    __shared__ int warp_sums[32];
    const int i = blockIdx.x * SCAN_CHUNK + threadIdx.x;
    const int lane = threadIdx.x & 31;
    const int warp = threadIdx.x >> 5;

    int v = (i < N_NODES) ? g_counts[i] : 0;
    int incl = v;
    #pragma unroll
    for (int off = 1; off < 32; off <<= 1) {
        int t = __shfl_up_sync(0xffffffffu, incl, off);
        if (lane >= off) incl += t;
    }
    if (lane == 31) warp_sums[warp] = incl;
    __syncthreads();
    if (warp == 0) {
        int w = warp_sums[lane];
        int wi = w;
        #pragma unroll
        for (int off = 1; off < 32; off <<= 1) {
            int t = __shfl_up_sync(0xffffffffu, wi, off);
            if (lane >= off) wi += t;
        }
        warp_sums[lane] = wi - w;
    }
    __syncthreads();

    if (i < N_NODES) {
        int o = g_chunk_base[blockIdx.x] + warp_sums[warp] + (incl - v);
        g_offsets[i] = o;
        g_cursor[i]  = o;
    }
}

__global__ void gcn_permute_kernel(const int*   __restrict__ edge_rows,
                                   const int*   __restrict__ edge_cols,
                                   const float* __restrict__ edge_vals)
{
    int e = blockIdx.x * blockDim.x + threadIdx.x;
    if (e < N_EDGES) {
        int r = edge_rows[e];
        int pos = atomicAdd(&g_cursor[r], 1);
        g_sorted_cols[pos] = edge_cols[e];
        g_sorted_vals[pos] = edge_vals[e];
    }
}

// ---------------------------------------------------------------------------
// Aggregate: one warp per node. Lane l owns features [4l, 4l+4).
// ---------------------------------------------------------------------------
__global__ __launch_bounds__(256) void gcn_aggregate_kernel(
    float* __restrict__ out,
    const float* __restrict__ bias)
{
    const int warp_id = (blockIdx.x * blockDim.x + threadIdx.x) >> 5;
    const int lane    = threadIdx.x & 31;
    if (warp_id >= N_NODES) return;

    const int start = g_offsets[warp_id];
    const int end   = g_offsets[warp_id + 1];

    float4 acc = make_float4(0.f, 0.f, 0.f, 0.f);

    for (int base = start; base < end; base += 32) {
        const int n = min(32, end - base);
        int   c = 0;
        float v = 0.f;
        if (lane < n) {
            c = __ldg(g_sorted_cols + base + lane);
            v = __ldg(g_sorted_vals + base + lane);
        }
        for (int j = 0; j < n; j++) {
            const int   cj = __shfl_sync(0xffffffffu, c, j);
            const float vj = __shfl_sync(0xffffffffu, v, j);
            const float4 m = __ldg(((const float4*)g_support) + (size_t)cj * 32 + lane);
            acc.x = fmaf(vj, m.x, acc.x);
            acc.y = fmaf(vj, m.y, acc.y);
            acc.z = fmaf(vj, m.z, acc.z);
            acc.w = fmaf(vj, m.w, acc.w);
        }
    }

    const float4 b = __ldg(((const float4*)bias) + lane);
    acc.x += b.x; acc.y += b.y; acc.z += b.z; acc.w += b.w;
    ((float4*)out)[(size_t)warp_id * 32 + lane] = acc;
}

// ---------------------------------------------------------------------------
// kernel_launch
// Inputs (metadata order): x, edge_rows, edge_cols, edge_vals, weight, bias
// ---------------------------------------------------------------------------
extern "C" void kernel_launch(void* const* d_in, const int* in_sizes, int n_in,
                              void* d_out, int out_size)
{
    const float* x         = (const float*)d_in[0];
    const int*   edge_rows = (const int*)  d_in[1];
    const int*   edge_cols = (const int*)  d_in[2];
    const float* edge_vals = (const float*)d_in[3];
    const float* weight    = (const float*)d_in[4];
    const float* bias      = (const float*)d_in[5];
    float*       out       = (float*)d_out;

    // 1) support = x @ W  (tcgen05 TF32x3 on sm_103a; FFMA fallback otherwise)
    static bool attr_set = false;
    if (!attr_set) {
        cudaFuncSetAttribute(gcn_gemm_tc_kernel,
                             cudaFuncAttributeMaxDynamicSharedMemorySize, SM_TOTAL);
        attr_set = true;
    }
    gcn_gemm_tc_kernel<<<(N_NODES + 127) / 128, 256, SM_TOTAL>>>(x, weight);

    // 2) CSR build
    gcn_zero_counts_kernel<<<(N_NODES + 255) / 256, 256>>>();
    gcn_histogram_kernel<<<(N_EDGES + 255) / 256, 256>>>(edge_rows);
    gcn_scan_reduce_kernel<<<NUM_CHUNKS, 1024>>>();
    gcn_scan_partials_kernel<<<1, 64>>>();
    gcn_scan_final_kernel<<<NUM_CHUNKS, 1024>>>();
    gcn_permute_kernel<<<(N_EDGES + 255) / 256, 256>>>(edge_rows, edge_cols, edge_vals);

    // 3) aggregate + bias
    {
        const int warps_per_block = 256 / 32;
        const int blocks = (N_NODES + warps_per_block - 1) / warps_per_block;
        gcn_aggregate_kernel<<<blocks, 256>>>(out, bias);
    }
}